// round 1
// baseline (speedup 1.0000x reference)
#include <cuda_runtime.h>
#include <math.h>

// Problem constants
constexpr int Bb  = 8;
constexpr int SEQ = 1024;
constexpr int ED  = 512;   // embed dim == key dim == value dim
constexpr int Hh  = 8;
constexpr int DH  = 64;
constexpr int Mrows = Bb * SEQ;   // 8192
constexpr int KD = 512;
constexpr int ND = 512;
constexpr float SCALE = 0.04419417382415922f;   // 1/sqrt(512)

// Scratch (device globals: allocation-free rule)
__device__ float g_q[Mrows * ND];
__device__ float g_k[Mrows * ND];
__device__ float g_v[Mrows * ND];
__device__ float g_o[Mrows * ND];

// ---------------------------------------------------------------------------
// 64x64-tile SGEMM body: C[M,N] = A[M,K] @ W[K,N] + bias
// 256 threads, each computes a 4x4 micro-tile. K-step 16.
// ---------------------------------------------------------------------------
__device__ __forceinline__ void gemm64_body(const float* __restrict__ A,
                                            const float* __restrict__ W,
                                            const float* __restrict__ bias,
                                            float* __restrict__ C)
{
    __shared__ float As[16][68];   // [k][m], padded to dodge store conflicts
    __shared__ float Bs[16][64];   // [k][n]

    const int t  = threadIdx.x;
    const int tx = t & 15;
    const int ty = t >> 4;
    const int m0 = blockIdx.y * 64;
    const int n0 = blockIdx.x * 64;

    float acc[4][4] = {};

    for (int k0 = 0; k0 < KD; k0 += 16) {
        {   // A tile: 64 rows x 16 k  (256 float4 loads, transposed store)
            int r  = t >> 2;
            int c4 = (t & 3) << 2;
            float4 v = *(const float4*)(A + (size_t)(m0 + r) * KD + k0 + c4);
            As[c4 + 0][r] = v.x;
            As[c4 + 1][r] = v.y;
            As[c4 + 2][r] = v.z;
            As[c4 + 3][r] = v.w;
        }
        {   // W tile: 16 k x 64 n
            int r  = t >> 4;
            int c4 = (t & 15) << 2;
            *(float4*)&Bs[r][c4] =
                *(const float4*)(W + (size_t)(k0 + r) * ND + n0 + c4);
        }
        __syncthreads();

        #pragma unroll
        for (int k = 0; k < 16; k++) {
            float4 a = *(const float4*)&As[k][ty * 4];
            float4 b = *(const float4*)&Bs[k][tx * 4];
            float av[4] = {a.x, a.y, a.z, a.w};
            float bv[4] = {b.x, b.y, b.z, b.w};
            #pragma unroll
            for (int i = 0; i < 4; i++)
                #pragma unroll
                for (int j = 0; j < 4; j++)
                    acc[i][j] += av[i] * bv[j];
        }
        __syncthreads();
    }

    #pragma unroll
    for (int i = 0; i < 4; i++) {
        int row = m0 + ty * 4 + i;
        int col = n0 + tx * 4;
        float4 o;
        o.x = acc[i][0] + bias[col + 0];
        o.y = acc[i][1] + bias[col + 1];
        o.z = acc[i][2] + bias[col + 2];
        o.w = acc[i][3] + bias[col + 3];
        *(float4*)(C + (size_t)row * ND + col) = o;
    }
}

// Fused Q/K/V projections: gridDim.z picks which projection.
__global__ void qkv_gemm(const float* __restrict__ Xq,
                         const float* __restrict__ Xk,
                         const float* __restrict__ Xv,
                         const float* __restrict__ Wq, const float* __restrict__ bq,
                         const float* __restrict__ Wk, const float* __restrict__ bk,
                         const float* __restrict__ Wv, const float* __restrict__ bv)
{
    const float *A, *W, *bias;
    float* C;
    if (blockIdx.z == 0)      { A = Xq; W = Wq; bias = bq; C = g_q; }
    else if (blockIdx.z == 1) { A = Xk; W = Wk; bias = bk; C = g_k; }
    else                      { A = Xv; W = Wv; bias = bv; C = g_v; }
    gemm64_body(A, W, bias, C);
}

__global__ void out_gemm(const float* __restrict__ Wo,
                         const float* __restrict__ bo,
                         float* __restrict__ out)
{
    gemm64_body(g_o, Wo, bo, out);
}

// ---------------------------------------------------------------------------
// Flash-style attention. One block = one (b,h) x 64-query tile.
// Key tiles of 32. Online softmax. All smem static (~41KB).
// ---------------------------------------------------------------------------
__global__ void attn_kernel()
{
    __shared__ float QsT[64 * 64];   // [d][q]
    __shared__ float KsT[64 * 32];   // [d][k]
    __shared__ float Vs [32 * 64];   // [k][d]
    __shared__ float Ssm[64 * 33];   // scores / probs, padded stride 33
    __shared__ float mrow[64], lrow[64], frow[64];

    const int t  = threadIdx.x;
    const int tx = t & 15;
    const int ty = t >> 4;
    const int q0 = blockIdx.x * 64;
    const int b  = blockIdx.y >> 3;
    const int h  = blockIdx.y & 7;
    const size_t base = (size_t)b * SEQ * ND + (size_t)h * DH;

    // Load Q tile transposed: 64 q-rows x 64 d
    #pragma unroll
    for (int i = 0; i < 4; i++) {
        int idx = t + i * 256;
        int r   = idx >> 4;
        int c4  = (idx & 15) << 2;
        float4 v = *(const float4*)(g_q + base + (size_t)(q0 + r) * ND + c4);
        QsT[(c4 + 0) * 64 + r] = v.x;
        QsT[(c4 + 1) * 64 + r] = v.y;
        QsT[(c4 + 2) * 64 + r] = v.z;
        QsT[(c4 + 3) * 64 + r] = v.w;
    }
    if (t < 64) { mrow[t] = -1e30f; lrow[t] = 0.f; }

    float acc[4][4] = {};
    __syncthreads();

    for (int kt = 0; kt < 32; kt++) {
        const int k0 = kt * 32;

        // Load K (transposed) and V tiles: 32 rows x 64 d each
        #pragma unroll
        for (int i = 0; i < 2; i++) {
            int idx = t + i * 256;
            int r   = idx >> 4;
            int c4  = (idx & 15) << 2;
            float4 kv = *(const float4*)(g_k + base + (size_t)(k0 + r) * ND + c4);
            KsT[(c4 + 0) * 32 + r] = kv.x;
            KsT[(c4 + 1) * 32 + r] = kv.y;
            KsT[(c4 + 2) * 32 + r] = kv.z;
            KsT[(c4 + 3) * 32 + r] = kv.w;
            float4 vv = *(const float4*)(g_v + base + (size_t)(k0 + r) * ND + c4);
            *(float4*)&Vs[r * 64 + c4] = vv;
        }
        __syncthreads();

        // S = Q K^T (per-thread 4 rows x 2 cols)
        float s[4][2] = {};
        #pragma unroll
        for (int d = 0; d < 64; d++) {
            float4 a  = *(const float4*)&QsT[d * 64 + ty * 4];
            float2 bb = *(const float2*)&KsT[d * 32 + tx * 2];
            s[0][0] += a.x * bb.x;  s[0][1] += a.x * bb.y;
            s[1][0] += a.y * bb.x;  s[1][1] += a.y * bb.y;
            s[2][0] += a.z * bb.x;  s[2][1] += a.z * bb.y;
            s[3][0] += a.w * bb.x;  s[3][1] += a.w * bb.y;
        }
        #pragma unroll
        for (int i = 0; i < 4; i++) {
            Ssm[(ty * 4 + i) * 33 + tx * 2 + 0] = s[i][0] * SCALE;
            Ssm[(ty * 4 + i) * 33 + tx * 2 + 1] = s[i][1] * SCALE;
        }
        __syncthreads();

        // Online softmax stats: one thread per query row
        if (t < 64) {
            float mx = -1e30f;
            #pragma unroll
            for (int j = 0; j < 32; j++) mx = fmaxf(mx, Ssm[t * 33 + j]);
            float nm  = fmaxf(mrow[t], mx);
            float f   = __expf(mrow[t] - nm);
            float sum = 0.f;
            #pragma unroll
            for (int j = 0; j < 32; j++) {
                float p = __expf(Ssm[t * 33 + j] - nm);
                Ssm[t * 33 + j] = p;
                sum += p;
            }
            lrow[t] = lrow[t] * f + sum;
            mrow[t] = nm;
            frow[t] = f;
        }
        __syncthreads();

        // Rescale running output, accumulate P @ V
        float fr[4];
        #pragma unroll
        for (int i = 0; i < 4; i++) fr[i] = frow[ty * 4 + i];
        #pragma unroll
        for (int i = 0; i < 4; i++)
            #pragma unroll
            for (int j = 0; j < 4; j++) acc[i][j] *= fr[i];

        #pragma unroll
        for (int k = 0; k < 32; k++) {
            float p0 = Ssm[(ty * 4 + 0) * 33 + k];
            float p1 = Ssm[(ty * 4 + 1) * 33 + k];
            float p2 = Ssm[(ty * 4 + 2) * 33 + k];
            float p3 = Ssm[(ty * 4 + 3) * 33 + k];
            float4 v = *(const float4*)&Vs[k * 64 + tx * 4];
            acc[0][0] += p0 * v.x; acc[0][1] += p0 * v.y; acc[0][2] += p0 * v.z; acc[0][3] += p0 * v.w;
            acc[1][0] += p1 * v.x; acc[1][1] += p1 * v.y; acc[1][2] += p1 * v.z; acc[1][3] += p1 * v.w;
            acc[2][0] += p2 * v.x; acc[2][1] += p2 * v.y; acc[2][2] += p2 * v.z; acc[2][3] += p2 * v.w;
            acc[3][0] += p3 * v.x; acc[3][1] += p3 * v.y; acc[3][2] += p3 * v.z; acc[3][3] += p3 * v.w;
        }
        __syncthreads();
    }

    // Normalize and write O (same layout as Q: [B,S, H*dh])
    #pragma unroll
    for (int i = 0; i < 4; i++) {
        float inv = 1.f / lrow[ty * 4 + i];
        float4 o;
        o.x = acc[i][0] * inv;
        o.y = acc[i][1] * inv;
        o.z = acc[i][2] * inv;
        o.w = acc[i][3] * inv;
        *(float4*)(g_o + base + (size_t)(q0 + ty * 4 + i) * ND + tx * 4) = o;
    }
}

// ---------------------------------------------------------------------------
extern "C" void kernel_launch(void* const* d_in, const int* in_sizes, int n_in,
                              void* d_out, int out_size)
{
    const float* q  = (const float*)d_in[0];
    const float* k  = (const float*)d_in[1];
    const float* v  = (const float*)d_in[2];
    const float* Wq = (const float*)d_in[3];
    const float* bq = (const float*)d_in[4];
    const float* Wk = (const float*)d_in[5];
    const float* bk = (const float*)d_in[6];
    const float* Wv = (const float*)d_in[7];
    const float* bv = (const float*)d_in[8];
    const float* Wo = (const float*)d_in[9];
    const float* bo = (const float*)d_in[10];

    qkv_gemm<<<dim3(ND / 64, Mrows / 64, 3), 256>>>(q, k, v, Wq, bq, Wk, bk, Wv, bv);
    attn_kernel<<<dim3(SEQ / 64, Bb * Hh), 256>>>();
    out_gemm<<<dim3(ND / 64, Mrows / 64), 256>>>(Wo, bo, (float*)d_out);
}

// round 3
// speedup vs baseline: 2.9860x; 2.9860x over previous
#include <cuda_runtime.h>
#include <cstdint>
#include <math.h>

// Problem constants
constexpr int Bb  = 8;
constexpr int SEQ = 1024;
constexpr int Hh  = 8;
constexpr int DH  = 64;
constexpr int Mrows = Bb * SEQ;   // 8192
constexpr int KD = 512;
constexpr int ND = 512;
constexpr float SCALE = 0.04419417382415922f;   // 1/sqrt(512)

// Scratch (device globals: allocation-free rule)
__device__ float g_q[Mrows * ND];
__device__ float g_k[Mrows * ND];
__device__ float g_v[Mrows * ND];
__device__ float g_o[Mrows * ND];
__device__ float g_wt[4][KD * ND];   // transposed weights: Wt[n][k]

// ---------------------------------------------------------------------------
// mma.sync tf32 helpers (sm_80+ PTX — compiles for plain sm_103)
// ---------------------------------------------------------------------------
__device__ __forceinline__ uint32_t f2tf32(float x) {
    uint32_t r;
    asm("cvt.rna.tf32.f32 %0, %1;" : "=r"(r) : "f"(x));
    return r;
}

__device__ __forceinline__ void mma_tf32(float c[4], const uint32_t a[4],
                                         const uint32_t b[2]) {
    asm volatile(
        "mma.sync.aligned.m16n8k8.row.col.f32.tf32.tf32.f32 "
        "{%0,%1,%2,%3}, {%4,%5,%6,%7}, {%8,%9}, {%0,%1,%2,%3};"
        : "+f"(c[0]), "+f"(c[1]), "+f"(c[2]), "+f"(c[3])
        : "r"(a[0]), "r"(a[1]), "r"(a[2]), "r"(a[3]),
          "r"(b[0]), "r"(b[1]));
}

// ---------------------------------------------------------------------------
// Weight transpose: Wt[n][k] = W[k][n]  (512x512 each, z selects matrix)
// ---------------------------------------------------------------------------
__global__ void transposeW(const float* __restrict__ Wq,
                           const float* __restrict__ Wk,
                           const float* __restrict__ Wv,
                           const float* __restrict__ Wo)
{
    __shared__ float tile[32][33];
    const float* src;
    switch (blockIdx.z) {
        case 0: src = Wq; break;
        case 1: src = Wk; break;
        case 2: src = Wv; break;
        default: src = Wo; break;
    }
    float* dst = g_wt[blockIdx.z];

    int x = blockIdx.x * 32 + threadIdx.x;
    int y = blockIdx.y * 32 + threadIdx.y;
    #pragma unroll
    for (int j = 0; j < 32; j += 8)
        tile[threadIdx.y + j][threadIdx.x] = src[(size_t)(y + j) * ND + x];
    __syncthreads();
    int x2 = blockIdx.y * 32 + threadIdx.x;
    int y2 = blockIdx.x * 32 + threadIdx.y;
    #pragma unroll
    for (int j = 0; j < 32; j += 8)
        dst[(size_t)(y2 + j) * KD + x2] = tile[threadIdx.x][threadIdx.y + j];
}

// ---------------------------------------------------------------------------
// tf32 mma GEMM: C[128,128] tile = A[M,512] @ Bt[N,512]^T + bias
// 256 threads = 8 warps (4m x 2n); warp tile 32m x 64n; K-chunk 32.
// A, Bt both K-major. tf32 rounding applied at smem store.
// ---------------------------------------------------------------------------
constexpr int GS = 36;   // smem row stride (floats): (36*g + tig) % 32 conflict-free

__device__ __forceinline__ void gemm_mma_body(const float* __restrict__ A,
                                              const float* __restrict__ Bt,
                                              const float* __restrict__ bias,
                                              float* __restrict__ C)
{
    __shared__ float sA[128 * GS];
    __shared__ float sB[128 * GS];

    const int t   = threadIdx.x;
    const int wid = t >> 5;
    const int lid = t & 31;
    const int g   = lid >> 2;   // groupID (row within fragment)
    const int tig = lid & 3;    // thread-in-group (col within fragment)
    const int wm  = wid & 3;    // warp m index (0..3)
    const int wn  = wid >> 2;   // warp n index (0..1)
    const int m0  = blockIdx.y * 128;
    const int n0  = blockIdx.x * 128;

    float acc[2][8][4] = {};

    for (int k0 = 0; k0 < KD; k0 += 32) {
        // Load A and B tiles: each 128 rows x 32 K-floats, tf32-rounded
        #pragma unroll
        for (int i = 0; i < 4; i++) {
            int idx = t + i * 256;        // 0..1023
            int r   = idx >> 3;           // 0..127
            int c4  = (idx & 7) << 2;     // 0,4,...,28
            float4 va = *(const float4*)(A  + (size_t)(m0 + r) * KD + k0 + c4);
            float4 vb = *(const float4*)(Bt + (size_t)(n0 + r) * KD + k0 + c4);
            float* pa = &sA[r * GS + c4];
            float* pb = &sB[r * GS + c4];
            pa[0] = __uint_as_float(f2tf32(va.x));
            pa[1] = __uint_as_float(f2tf32(va.y));
            pa[2] = __uint_as_float(f2tf32(va.z));
            pa[3] = __uint_as_float(f2tf32(va.w));
            pb[0] = __uint_as_float(f2tf32(vb.x));
            pb[1] = __uint_as_float(f2tf32(vb.y));
            pb[2] = __uint_as_float(f2tf32(vb.z));
            pb[3] = __uint_as_float(f2tf32(vb.w));
        }
        __syncthreads();

        #pragma unroll
        for (int ks = 0; ks < 4; ks++) {
            const int kk = ks * 8;
            uint32_t afr[2][4];
            #pragma unroll
            for (int mt = 0; mt < 2; mt++) {
                int row = (wm * 32 + mt * 16 + g) * GS + kk + tig;
                afr[mt][0] = __float_as_uint(sA[row]);
                afr[mt][1] = __float_as_uint(sA[row + 8 * GS]);
                afr[mt][2] = __float_as_uint(sA[row + 4]);
                afr[mt][3] = __float_as_uint(sA[row + 8 * GS + 4]);
            }
            uint32_t bfr[8][2];
            #pragma unroll
            for (int nt = 0; nt < 8; nt++) {
                int rowb = (wn * 64 + nt * 8 + g) * GS + kk + tig;
                bfr[nt][0] = __float_as_uint(sB[rowb]);
                bfr[nt][1] = __float_as_uint(sB[rowb + 4]);
            }
            #pragma unroll
            for (int mt = 0; mt < 2; mt++)
                #pragma unroll
                for (int nt = 0; nt < 8; nt++)
                    mma_tf32(acc[mt][nt], afr[mt], bfr[nt]);
        }
        __syncthreads();
    }

    // Epilogue
    #pragma unroll
    for (int mt = 0; mt < 2; mt++) {
        int row = m0 + wm * 32 + mt * 16 + g;
        #pragma unroll
        for (int nt = 0; nt < 8; nt++) {
            int col = n0 + wn * 64 + nt * 8 + tig * 2;
            float2 o0, o1;
            o0.x = acc[mt][nt][0] + bias[col];
            o0.y = acc[mt][nt][1] + bias[col + 1];
            o1.x = acc[mt][nt][2] + bias[col];
            o1.y = acc[mt][nt][3] + bias[col + 1];
            *(float2*)(C + (size_t)row * ND + col)       = o0;
            *(float2*)(C + (size_t)(row + 8) * ND + col) = o1;
        }
    }
}

__global__ void __launch_bounds__(256)
qkv_mma(const float* __restrict__ Xq, const float* __restrict__ Xk,
        const float* __restrict__ Xv,
        const float* __restrict__ bq, const float* __restrict__ bk,
        const float* __restrict__ bv)
{
    const float* A;
    const float* bias;
    float* C;
    if (blockIdx.z == 0)      { A = Xq; bias = bq; C = g_q; }
    else if (blockIdx.z == 1) { A = Xk; bias = bk; C = g_k; }
    else                      { A = Xv; bias = bv; C = g_v; }
    gemm_mma_body(A, g_wt[blockIdx.z], bias, C);
}

__global__ void __launch_bounds__(256)
out_mma(const float* __restrict__ bo, float* __restrict__ out)
{
    gemm_mma_body(g_o, g_wt[3], bo, out);
}

// ---------------------------------------------------------------------------
// Flash attention with tf32 mma. One block = (b,h) x 64 queries, 128 threads.
// Key tiles of 32. S and P@V on tensor cores; softmax on smem.
// ---------------------------------------------------------------------------
constexpr int AS = 68;   // stride for Qs/Ks/Vs
constexpr int SS = 36;   // stride for Ssm

__global__ void __launch_bounds__(128) attn_mma()
{
    __shared__ float Qs[64 * AS];    // [q][d], pre-scaled, tf32-rounded
    __shared__ float Ks[32 * AS];    // [key][d], tf32-rounded
    __shared__ float Vs[32 * AS];    // [key][d], tf32-rounded
    __shared__ float Ssm[64 * SS];   // [q][key]
    __shared__ float mrow[64], lrow[64], frow[64];

    const int t   = threadIdx.x;
    const int wid = t >> 5;
    const int lid = t & 31;
    const int g   = lid >> 2;
    const int tig = lid & 3;
    const int q0  = blockIdx.x * 64;
    const int b   = blockIdx.y >> 3;
    const int h   = blockIdx.y & 7;
    const size_t base = (size_t)b * SEQ * ND + (size_t)h * DH;

    // Load Q tile: 64 q-rows x 64 d, pre-scaled by SCALE, tf32-rounded
    #pragma unroll
    for (int i = 0; i < 8; i++) {
        int idx = t + i * 128;        // 0..1023
        int r   = idx >> 4;           // 0..63
        int c4  = (idx & 15) << 2;    // 0..60
        float4 v = *(const float4*)(g_q + base + (size_t)(q0 + r) * ND + c4);
        float* p = &Qs[r * AS + c4];
        p[0] = __uint_as_float(f2tf32(v.x * SCALE));
        p[1] = __uint_as_float(f2tf32(v.y * SCALE));
        p[2] = __uint_as_float(f2tf32(v.z * SCALE));
        p[3] = __uint_as_float(f2tf32(v.w * SCALE));
    }
    if (t < 64) { mrow[t] = -1e30f; lrow[t] = 0.f; }

    float oacc[8][4] = {};   // O fragments: 8 n-tiles (d=64), warp's 16 q rows
    __syncthreads();

    const int qrow = wid * 16 + g;   // this thread's first q row (second: +8)

    for (int kt = 0; kt < 32; kt++) {
        const int k0 = kt * 32;

        // Load K and V tiles: 32 rows x 64 d each, tf32-rounded
        #pragma unroll
        for (int i = 0; i < 4; i++) {
            int idx = t + i * 128;
            int r   = idx >> 4;
            int c4  = (idx & 15) << 2;
            float4 kv = *(const float4*)(g_k + base + (size_t)(k0 + r) * ND + c4);
            float4 vv = *(const float4*)(g_v + base + (size_t)(k0 + r) * ND + c4);
            float* pk = &Ks[r * AS + c4];
            float* pv = &Vs[r * AS + c4];
            pk[0] = __uint_as_float(f2tf32(kv.x));
            pk[1] = __uint_as_float(f2tf32(kv.y));
            pk[2] = __uint_as_float(f2tf32(kv.z));
            pk[3] = __uint_as_float(f2tf32(kv.w));
            pv[0] = __uint_as_float(f2tf32(vv.x));
            pv[1] = __uint_as_float(f2tf32(vv.y));
            pv[2] = __uint_as_float(f2tf32(vv.z));
            pv[3] = __uint_as_float(f2tf32(vv.w));
        }
        __syncthreads();

        // S = (Q*SCALE) @ K^T : warp computes 16 q-rows x 32 keys
        float sfr[4][4] = {};
        #pragma unroll
        for (int ks = 0; ks < 8; ks++) {
            const int kk = ks * 8;
            uint32_t afr[4];
            int ra = qrow * AS + kk + tig;
            afr[0] = __float_as_uint(Qs[ra]);
            afr[1] = __float_as_uint(Qs[ra + 8 * AS]);
            afr[2] = __float_as_uint(Qs[ra + 4]);
            afr[3] = __float_as_uint(Qs[ra + 8 * AS + 4]);
            #pragma unroll
            for (int nt = 0; nt < 4; nt++) {
                uint32_t bfr[2];
                int rb = (nt * 8 + g) * AS + kk + tig;
                bfr[0] = __float_as_uint(Ks[rb]);
                bfr[1] = __float_as_uint(Ks[rb + 4]);
                mma_tf32(sfr[nt], afr, bfr);
            }
        }
        // Store S fragments to smem
        #pragma unroll
        for (int nt = 0; nt < 4; nt++) {
            int col = nt * 8 + tig * 2;
            *(float2*)&Ssm[qrow * SS + col]       = make_float2(sfr[nt][0], sfr[nt][1]);
            *(float2*)&Ssm[(qrow + 8) * SS + col] = make_float2(sfr[nt][2], sfr[nt][3]);
        }
        __syncthreads();

        // Online softmax: one thread per query row; store P tf32-rounded
        if (t < 64) {
            float mx = -1e30f;
            #pragma unroll
            for (int j = 0; j < 32; j++) mx = fmaxf(mx, Ssm[t * SS + j]);
            float nm  = fmaxf(mrow[t], mx);
            float f   = __expf(mrow[t] - nm);
            float sum = 0.f;
            #pragma unroll
            for (int j = 0; j < 32; j++) {
                float p = __expf(Ssm[t * SS + j] - nm);
                sum += p;
                Ssm[t * SS + j] = __uint_as_float(f2tf32(p));
            }
            lrow[t] = lrow[t] * f + sum;
            mrow[t] = nm;
            frow[t] = f;
        }
        __syncthreads();

        // Rescale running O, then accumulate P @ V
        float f0 = frow[qrow];
        float f1 = frow[qrow + 8];
        #pragma unroll
        for (int nt = 0; nt < 8; nt++) {
            oacc[nt][0] *= f0;  oacc[nt][1] *= f0;
            oacc[nt][2] *= f1;  oacc[nt][3] *= f1;
        }
        #pragma unroll
        for (int ks = 0; ks < 4; ks++) {
            const int kk = ks * 8;
            uint32_t afr[4];
            int ra = qrow * SS + kk + tig;
            afr[0] = __float_as_uint(Ssm[ra]);
            afr[1] = __float_as_uint(Ssm[ra + 8 * SS]);
            afr[2] = __float_as_uint(Ssm[ra + 4]);
            afr[3] = __float_as_uint(Ssm[ra + 8 * SS + 4]);
            #pragma unroll
            for (int nt = 0; nt < 8; nt++) {
                uint32_t bfr[2];
                int rb = (kk + tig) * AS + nt * 8 + g;
                bfr[0] = __float_as_uint(Vs[rb]);
                bfr[1] = __float_as_uint(Vs[rb + 4 * AS]);
                mma_tf32(oacc[nt], afr, bfr);
            }
        }
        __syncthreads();
    }

    // Normalize and write O
    float inv0 = 1.f / lrow[qrow];
    float inv1 = 1.f / lrow[qrow + 8];
    #pragma unroll
    for (int nt = 0; nt < 8; nt++) {
        int col = nt * 8 + tig * 2;
        float2 o0 = make_float2(oacc[nt][0] * inv0, oacc[nt][1] * inv0);
        float2 o1 = make_float2(oacc[nt][2] * inv1, oacc[nt][3] * inv1);
        *(float2*)(g_o + base + (size_t)(q0 + qrow) * ND + col)     = o0;
        *(float2*)(g_o + base + (size_t)(q0 + qrow + 8) * ND + col) = o1;
    }
}

// ---------------------------------------------------------------------------
extern "C" void kernel_launch(void* const* d_in, const int* in_sizes, int n_in,
                              void* d_out, int out_size)
{
    const float* q  = (const float*)d_in[0];
    const float* k  = (const float*)d_in[1];
    const float* v  = (const float*)d_in[2];
    const float* Wq = (const float*)d_in[3];
    const float* bq = (const float*)d_in[4];
    const float* Wk = (const float*)d_in[5];
    const float* bk = (const float*)d_in[6];
    const float* Wv = (const float*)d_in[7];
    const float* bv = (const float*)d_in[8];
    const float* Wo = (const float*)d_in[9];
    const float* bo = (const float*)d_in[10];

    transposeW<<<dim3(16, 16, 4), dim3(32, 8)>>>(Wq, Wk, Wv, Wo);
    qkv_mma<<<dim3(ND / 128, Mrows / 128, 3), 256>>>(q, k, v, bq, bk, bv);
    attn_mma<<<dim3(SEQ / 64, Bb * Hh), 128>>>();
    out_mma<<<dim3(ND / 128, Mrows / 128), 256>>>(bo, (float*)d_out);
}